// round 4
// baseline (speedup 1.0000x reference)
#include <cuda_runtime.h>

#define BN 128   // n rows per block
#define BM 64    // m cols per block
#define TN 8     // n per thread
#define TM 4     // m per thread
#define DD 64    // feature dim
#define C4 16    // DD/4 float4 chunks
#define THREADS 256

// smem layout (dynamic): xs[16][128] float4 | ws[16][64] float4 | Sx[128] | Sw[64]
#define XS_OFF 0
#define WS_OFF (C4 * BN)            // in float4 units
#define SMEM_F4 (C4 * (BN + BM))    // float4 count for tiles
#define SMEM_BYTES (SMEM_F4 * 16 + (BN + BM) * 4)

// acc = m * 1.0f + acc  -> FFMA-imm form (rt_SMSP=1)
__device__ __forceinline__ void ffma_acc1(float &acc, float m) {
    asm("fma.rn.f32 %0, %1, 0f3F800000, %0;" : "+f"(acc) : "f"(m));
}

__global__ __launch_bounds__(THREADS, 2)
void cdist_l1_kernel(const float4* __restrict__ x4,
                     const float4* __restrict__ w4,
                     float* __restrict__ out,
                     int Mtot)
{
    extern __shared__ float4 smem[];
    float4* xs = smem + XS_OFF;                     // [c][n] : xs[c*BN + n]
    float4* ws = smem + WS_OFF;                     // [c][m] : ws[c*BM + m]
    float*  Sx = (float*)(smem + SMEM_F4);          // [BN]
    float*  Sw = Sx + BN;                           // [BM]

    const int tid = threadIdx.x;
    const int n0 = blockIdx.y * BN;
    const int m0 = blockIdx.x * BM;

    // ---- load x tile: BN x C4 = 2048 float4, 8 per thread ----
    #pragma unroll
    for (int i = 0; i < (BN * C4) / THREADS; i++) {   // 8
        int idx = tid + i * THREADS;
        int n  = idx & (BN - 1);
        int c  = idx >> 7;
        xs[c * BN + n] = x4[(size_t)(n0 + n) * C4 + c];
    }
    // ---- load w tile: BM x C4 = 1024 float4, 4 per thread ----
    #pragma unroll
    for (int i = 0; i < (BM * C4) / THREADS; i++) {   // 4
        int idx = tid + i * THREADS;
        int m  = idx & (BM - 1);
        int c  = idx >> 6;
        ws[c * BM + m] = w4[(size_t)(m0 + m) * C4 + c];
    }
    __syncthreads();

    // ---- per-row sums (one row per thread, threads 0..191) ----
    if (tid < BN) {
        float s = 0.f;
        #pragma unroll
        for (int c = 0; c < C4; c++) {
            float4 v = xs[c * BN + tid];
            s += (v.x + v.y) + (v.z + v.w);
        }
        Sx[tid] = s;
    } else if (tid < BN + BM) {
        int m = tid - BN;
        float s = 0.f;
        #pragma unroll
        for (int c = 0; c < C4; c++) {
            float4 v = ws[c * BM + m];
            s += (v.x + v.y) + (v.z + v.w);
        }
        Sw[m] = s;
    }

    const int tx = tid & 15;   // m: tx + j*16
    const int ty = tid >> 4;   // n: ty*8 + i

    // acc[i][j] accumulates sum_d max(x_d, w_d)
    float acc[TN][TM];
    #pragma unroll
    for (int i = 0; i < TN; i++)
        #pragma unroll
        for (int j = 0; j < TM; j++) acc[i][j] = 0.f;

    #pragma unroll 2
    for (int c = 0; c < C4; c++) {
        float4 xr[TN], wr[TM];
        #pragma unroll
        for (int i = 0; i < TN; i++) xr[i] = xs[c * BN + ty * TN + i];
        #pragma unroll
        for (int j = 0; j < TM; j++) wr[j] = ws[c * BM + j * 16 + tx];
        // 256 FMNMX (alu, rt2) + 128 FFMA-imm (fma, rt1) per chunk
        #pragma unroll
        for (int i = 0; i < TN; i++)
            #pragma unroll
            for (int j = 0; j < TM; j++) {
                ffma_acc1(acc[i][j], fmaxf(xr[i].x, wr[j].x));
                ffma_acc1(acc[i][j], fmaxf(xr[i].y, wr[j].y));
                ffma_acc1(acc[i][j], fmaxf(xr[i].z, wr[j].z));
                ffma_acc1(acc[i][j], fmaxf(xr[i].w, wr[j].w));
            }
    }

    __syncthreads();   // Sx/Sw visibility

    // ---- epilogue: out[n][m] = Sx[n] + Sw[m] - 2*sum_max ----
    float sxr[TN], swr[TM];
    #pragma unroll
    for (int i = 0; i < TN; i++) sxr[i] = Sx[ty * TN + i];
    #pragma unroll
    for (int j = 0; j < TM; j++) swr[j] = Sw[j * 16 + tx];

    #pragma unroll
    for (int i = 0; i < TN; i++) {
        const size_t nrow = (size_t)(n0 + ty * TN + i) * (size_t)Mtot;
        #pragma unroll
        for (int j = 0; j < TM; j++) {
            out[nrow + m0 + j * 16 + tx] = fmaf(-2.f, acc[i][j], sxr[i] + swr[j]);
        }
    }
}

extern "C" void kernel_launch(void* const* d_in, const int* in_sizes, int n_in,
                              void* d_out, int out_size) {
    const float4* x4 = (const float4*)d_in[0];   // [N, 64] fp32
    const float4* w4 = (const float4*)d_in[1];   // [M, 64] fp32
    float* out = (float*)d_out;                  // [N, M] fp32

    const int N = in_sizes[0] / DD;   // 8192
    const int M = in_sizes[1] / DD;   // 1024

    static int smem_set = 0;
    if (!smem_set) {
        cudaFuncSetAttribute(cdist_l1_kernel,
                             cudaFuncAttributeMaxDynamicSharedMemorySize,
                             SMEM_BYTES);
        smem_set = 1;
    }

    dim3 grid(M / BM, N / BN);        // (16, 64)
    cdist_l1_kernel<<<grid, THREADS, SMEM_BYTES>>>(x4, w4, out, M);
}

// round 5
// speedup vs baseline: 1.3761x; 1.3761x over previous
#include <cuda_runtime.h>

#define BN 64    // n rows per block
#define BM 64    // m cols per block
#define TN 4     // n per thread
#define TM 4     // m per thread
#define DD 64    // feature dim
#define C4 16    // DD/4 float4 chunks
#define THREADS 256

// x-row n lives at smem slot ((n&3)<<4)|(n>>2).
// Mainloop reads xs[c][i*16 + ty]  (lane stride 16B -> conflict-free).
#define SLOT(n) (((((n) & 3)) << 4) | ((n) >> 2))

// acc = m * 1.0f + acc  -> FFMA-imm form (rt_SMSP=1)
__device__ __forceinline__ void ffma_acc1(float &acc, float m) {
    asm("fma.rn.f32 %0, %1, 0f3F800000, %0;" : "+f"(acc) : "f"(m));
}

__global__ __launch_bounds__(THREADS, 4)
void cdist_l1_kernel(const float4* __restrict__ x4,
                     const float4* __restrict__ w4,
                     float* __restrict__ out,
                     int Mtot)
{
    __shared__ float4 xs[C4][BN];   // slot-permuted rows
    __shared__ float4 ws[C4][BM];
    __shared__ float Sx[BN];        // row sums of x tile (true row index)
    __shared__ float Sw[BM];

    const int tid = threadIdx.x;
    const int n0 = blockIdx.y * BN;
    const int m0 = blockIdx.x * BM;

    // ---- load x tile: 1024 float4, 4 per thread (stores slot-permuted) ----
    #pragma unroll
    for (int i = 0; i < (BN * C4) / THREADS; i++) {   // 4
        int idx = tid + i * THREADS;
        int n  = idx & (BN - 1);
        int c  = idx >> 6;
        xs[c][SLOT(n)] = x4[(size_t)(n0 + n) * C4 + c];
    }
    // ---- load w tile: 1024 float4, 4 per thread ----
    #pragma unroll
    for (int i = 0; i < (BM * C4) / THREADS; i++) {   // 4
        int idx = tid + i * THREADS;
        int m  = idx & (BM - 1);
        int c  = idx >> 6;
        ws[c][m] = w4[(size_t)(m0 + m) * C4 + c];
    }
    __syncthreads();

    // ---- per-row sums (one-time) ----
    if (tid < BN) {
        float s = 0.f;
        #pragma unroll
        for (int c = 0; c < C4; c++) {
            float4 v = xs[c][SLOT(tid)];
            s += (v.x + v.y) + (v.z + v.w);
        }
        Sx[tid] = s;
    } else if (tid < BN + BM) {
        int m = tid - BN;
        float s = 0.f;
        #pragma unroll
        for (int c = 0; c < C4; c++) {
            float4 v = ws[c][m];
            s += (v.x + v.y) + (v.z + v.w);
        }
        Sw[m] = s;
    }

    const int tx = tid & 15;   // m: tx + j*16  (conflict-free ws, coalesced out)
    const int ty = tid >> 4;   // n: ty*4 + i   (slot i*16+ty -> conflict-free xs)

    // acc[i][j] accumulates sum_d max(x_d, w_d)
    float acc[TN][TM];
    #pragma unroll
    for (int i = 0; i < TN; i++)
        #pragma unroll
        for (int j = 0; j < TM; j++) acc[i][j] = 0.f;

    #pragma unroll 4
    for (int c = 0; c < C4; c++) {
        float4 xr[TN], wr[TM];
        #pragma unroll
        for (int i = 0; i < TN; i++) xr[i] = xs[c][i * 16 + ty];  // slot of n=ty*4+i
        #pragma unroll
        for (int j = 0; j < TM; j++) wr[j] = ws[c][j * 16 + tx];
        #pragma unroll
        for (int i = 0; i < TN; i++)
            #pragma unroll
            for (int j = 0; j < TM; j++) {
                ffma_acc1(acc[i][j], fmaxf(xr[i].x, wr[j].x));  // FMNMX(alu,rt2)+FFMA-imm(fma,rt1)
                ffma_acc1(acc[i][j], fmaxf(xr[i].y, wr[j].y));
                ffma_acc1(acc[i][j], fmaxf(xr[i].z, wr[j].z));
                ffma_acc1(acc[i][j], fmaxf(xr[i].w, wr[j].w));
            }
    }

    __syncthreads();   // Sx/Sw visibility

    // ---- epilogue: out[n][m] = Sx[n] + Sw[m] - 2*sum_max ----
    float sxr[TN], swr[TM];
    #pragma unroll
    for (int i = 0; i < TN; i++) sxr[i] = Sx[ty * TN + i];
    #pragma unroll
    for (int j = 0; j < TM; j++) swr[j] = Sw[j * 16 + tx];

    #pragma unroll
    for (int i = 0; i < TN; i++) {
        const size_t nrow = (size_t)(n0 + ty * TN + i) * (size_t)Mtot;
        #pragma unroll
        for (int j = 0; j < TM; j++) {
            out[nrow + m0 + j * 16 + tx] = fmaf(-2.f, acc[i][j], sxr[i] + swr[j]);
        }
    }
}

extern "C" void kernel_launch(void* const* d_in, const int* in_sizes, int n_in,
                              void* d_out, int out_size) {
    const float4* x4 = (const float4*)d_in[0];   // [N, 64] fp32
    const float4* w4 = (const float4*)d_in[1];   // [M, 64] fp32
    float* out = (float*)d_out;                  // [N, M] fp32

    const int N = in_sizes[0] / DD;   // 8192
    const int M = in_sizes[1] / DD;   // 1024

    dim3 grid(M / BM, N / BN);        // (16, 128)
    cdist_l1_kernel<<<grid, THREADS>>>(x4, w4, out, M);
}